// round 13
// baseline (speedup 1.0000x reference)
#include <cuda_runtime.h>
#include <cuda_fp16.h>
#include <math.h>
#include <stdint.h>

// ---------------- problem constants ----------------
#define NT   16384
#define NK   32768
#define D_   768
#define H_   2048
#define E_   8
#define CAP  5120
#define EPSF 1e-6f
#define N13  4096

#define RGN32 8192       // 128 rows * 64B region (KCH=32)
#define STG1  24576      // gemm1 stage: A(8K) + Bg(8K) + Bu(8K)
#define STG2  24576      // gemm2 stage: A(8K) + B(16K, 256 rows)
#define DSMEM 73728      // 3 stages

// ---------------- device scratch (referenced ONLY in device code) ----------------
__device__ float  g_scale[NT];
__device__ __half g_zh  [(size_t)E_ * CAP * D_];
__device__ __half g_w13h[(size_t)E_ * N13 * D_];
__device__ __half g_w2h [(size_t)E_ * D_ * H_];
__device__ __half g_acth[(size_t)E_ * CAP * H_];
__device__ float  g_ffn [(size_t)E_ * CAP * D_];
__device__ int    g_rowlist[E_ * CAP];
__device__ int    g_cnt[E_];
__device__ int    g_slot[NK];
__device__ int    g_expert[NK];
__device__ float  g_weight[NK];

// ---------------- helpers ----------------
__device__ __forceinline__ uint32_t smem_u32(const void* p) {
    uint32_t a;
    asm("{ .reg .u64 t; cvta.to.shared.u64 t, %1; cvt.u32.u64 %0, t; }" : "=r"(a) : "l"(p));
    return a;
}
__device__ __forceinline__ void ldsm4(uint32_t& r0, uint32_t& r1, uint32_t& r2, uint32_t& r3,
                                      uint32_t addr) {
    asm volatile("ldmatrix.sync.aligned.m8n8.x4.shared.b16 {%0,%1,%2,%3}, [%4];"
                 : "=r"(r0), "=r"(r1), "=r"(r2), "=r"(r3) : "r"(addr));
}
__device__ __forceinline__ void mma16816(float* d, const uint32_t* a, uint32_t b0, uint32_t b1) {
    asm volatile(
        "mma.sync.aligned.m16n8k16.row.col.f32.f16.f16.f32 "
        "{%0,%1,%2,%3},{%4,%5,%6,%7},{%8,%9},{%0,%1,%2,%3};"
        : "+f"(d[0]), "+f"(d[1]), "+f"(d[2]), "+f"(d[3])
        : "r"(a[0]), "r"(a[1]), "r"(a[2]), "r"(a[3]), "r"(b0), "r"(b1));
}
__device__ __forceinline__ void cp16(uint32_t saddr, const void* g) {
    asm volatile("cp.async.cg.shared.global [%0], [%1], 16;" :: "r"(saddr), "l"(g) : "memory");
}
__device__ __forceinline__ float silu_mul(float g, float u) {
    return u * (g / (1.f + expf(-g)));
}
// 64B-row swizzle: conflict-free for cp.async writes and ldmatrix reads
__device__ __forceinline__ uint32_t swz32(int row, int ch) {
    return (uint32_t)row * 64 + (uint32_t)((ch ^ ((row >> 1) & 3)) << 4);
}

// ---------------- 1) router + fused rms scale ----------------
__global__ void router_kernel(const float* __restrict__ x, const float* __restrict__ gw) {
    __shared__ float sgw[E_ * D_];
    for (int i = threadIdx.x; i < E_ * D_; i += 256) sgw[i] = gw[i];
    __syncthreads();
    int lane = threadIdx.x & 31, warp = threadIdx.x >> 5;
    int t = blockIdx.x * 8 + warp;
    const float* xp = x + (size_t)t * D_;
    float xr[24];
    float ss = 0.f;
    #pragma unroll
    for (int j = 0; j < 24; j++) { xr[j] = xp[lane + 32 * j]; ss += xr[j] * xr[j]; }
    for (int o = 16; o; o >>= 1) ss += __shfl_xor_sync(0xffffffffu, ss, o);
    float logit[E_];
    #pragma unroll
    for (int e = 0; e < E_; e++) {
        float acc = 0.f;
        #pragma unroll
        for (int j = 0; j < 24; j++) acc += xr[j] * sgw[e * D_ + lane + 32 * j];
        for (int o = 16; o; o >>= 1) acc += __shfl_xor_sync(0xffffffffu, acc, o);
        logit[e] = acc;
    }
    if (lane == 0) {
        g_scale[t] = 2.f * rsqrtf(4.f * ss / (float)D_ + EPSF);
        int i0 = 0; float l0 = logit[0];
        #pragma unroll
        for (int e = 1; e < E_; e++) if (logit[e] > l0) { l0 = logit[e]; i0 = e; }
        int i1 = -1; float l1 = -3.0e38f;
        #pragma unroll
        for (int e = 0; e < E_; e++) if (e != i0 && logit[e] > l1) { l1 = logit[e]; i1 = e; }
        float w0 = 1.f / (1.f + expf(l1 - l0));
        g_expert[2 * t]     = i0;
        g_expert[2 * t + 1] = i1;
        g_weight[2 * t]     = w0;
        g_weight[2 * t + 1] = 1.f - w0;
    }
}

// ---------------- 2) capacity scan ----------------
__global__ void scan_kernel() {
    int e = blockIdx.x;
    int tid = threadIdx.x;
    __shared__ int warpsum[8];
    __shared__ int sbase;
    if (tid == 0) sbase = 0;
    __syncthreads();
    for (int i0 = 0; i0 < NK; i0 += 256) {
        int i = i0 + tid;
        int mine = (g_expert[i] == e) ? 1 : 0;
        unsigned m = __ballot_sync(0xffffffffu, mine);
        int lane = tid & 31, w = tid >> 5;
        if (lane == 0) warpsum[w] = __popc(m);
        __syncthreads();
        int off = 0, tot = 0;
        #pragma unroll
        for (int j = 0; j < 8; j++) { int c = warpsum[j]; tot += c; if (j < w) off += c; }
        int rank = sbase + off + __popc(m & ((1u << lane) - 1u));
        if (mine) {
            if (rank < CAP) { g_rowlist[e * CAP + rank] = i; g_slot[i] = e * CAP + rank; }
            else            { g_slot[i] = -1; }
        }
        __syncthreads();
        if (tid == 0) sbase += tot;
    }
    __syncthreads();
    if (tid == 0) g_cnt[e] = (sbase < CAP) ? sbase : CAP;
}

// ---------------- 3) dispatch -> fp16 ----------------
__global__ void dispatch_kernel(const float* __restrict__ x, const float* __restrict__ norm_w) {
    int slot = blockIdx.x;
    int e = slot / CAP, r = slot % CAP;
    if (r >= g_cnt[e]) return;
    int t = g_rowlist[slot] >> 1;
    float sc = g_scale[t];
    int i = threadIdx.x;  // 192 threads * 4 = 768
    float4 a = ((const float4*)(x + (size_t)t * D_))[i];
    float4 b = ((const float4*)(norm_w + (size_t)e * D_))[i];
    union { __half h[4]; uint2 u; } Hh;
    Hh.h[0] = __float2half_rn(a.x * sc * b.x);
    Hh.h[1] = __float2half_rn(a.y * sc * b.y);
    Hh.h[2] = __float2half_rn(a.z * sc * b.z);
    Hh.h[3] = __float2half_rn(a.w * sc * b.w);
    ((uint2*)(g_zh + (size_t)slot * D_))[i] = Hh.u;
}

// ---------------- weights fp32 -> fp16 ----------------
__global__ void cvt_kernel(const float* __restrict__ src, int which) {
    __half* dst = which ? g_w2h : g_w13h;
    int i = blockIdx.x * 256 + threadIdx.x;
    float4 v = ((const float4*)src)[i];
    union { __half h[4]; uint2 u; } H;
    H.h[0] = __float2half_rn(v.x); H.h[1] = __float2half_rn(v.y);
    H.h[2] = __float2half_rn(v.z); H.h[3] = __float2half_rn(v.w);
    ((uint2*)dst)[i] = H.u;
}

// ---------------- 4) GEMM1 fused with silu (ldmatrix, KCH=32, 3-stage) -----
__global__ __launch_bounds__(256) void gemm1_silu()
{
    extern __shared__ __align__(16) char dyn[];

    int e = blockIdx.z;
    int m0 = blockIdx.y * 128;
    if (m0 >= g_cnt[e]) return;
    int n0 = blockIdx.x * 128;

    int tid = threadIdx.x, lane = tid & 31, wid = tid >> 5;
    int wm = wid & 1, wn = wid >> 1;
    int g = lane >> 2, q = lane & 3;

    const __half* pA  = g_zh   + ((size_t)e * CAP + m0) * D_;
    const __half* pBg = g_w13h + ((size_t)e * N13 + n0) * D_;
    const __half* pBu = g_w13h + ((size_t)e * N13 + H_ + n0) * D_;

    float accg[4][4][4], accu[4][4][4];
    #pragma unroll
    for (int i = 0; i < 4; i++)
        #pragma unroll
        for (int j = 0; j < 4; j++)
            #pragma unroll
            for (int p = 0; p < 4; p++) { accg[i][j][p] = 0.f; accu[i][j][p] = 0.f; }

    // loaders: 2 chunk-slots per thread per region (128 rows x 4 chunks)
    int i0_ld = tid * 2, i1_ld = tid * 2 + 1;
    int r0_ld = i0_ld >> 2, c0_ld = i0_ld & 3;
    int r1_ld = i1_ld >> 2, c1_ld = i1_ld & 3;
    uint32_t s0 = swz32(r0_ld, c0_ld), s1 = swz32(r1_ld, c1_ld);
    size_t g0 = (size_t)r0_ld * D_ + c0_ld * 8;
    size_t g1 = (size_t)r1_ld * D_ + c1_ld * 8;

    int a_rl = (lane & 7) + ((lane >> 3) & 1) * 8;
    int a_hc = lane >> 4;             // 16B half of the k16 tile
    int b_rl = lane & 7;
    int b_fr = lane >> 4;
    int b_hc = (lane >> 3) & 1;

    const int NCH = D_ >> 5;   // 24

    #pragma unroll
    for (int c = 0; c < 2; c++) {
        uint32_t sb = smem_u32(dyn + c * STG1);
        size_t ko = (size_t)c * 32;
        cp16(sb + s0,             pA  + g0 + ko);
        cp16(sb + s1,             pA  + g1 + ko);
        cp16(sb + RGN32 + s0,     pBg + g0 + ko);
        cp16(sb + RGN32 + s1,     pBg + g1 + ko);
        cp16(sb + 2 * RGN32 + s0, pBu + g0 + ko);
        cp16(sb + 2 * RGN32 + s1, pBu + g1 + ko);
        asm volatile("cp.async.commit_group;" ::: "memory");
    }

    for (int c = 0; c < NCH; c++) {
        asm volatile("cp.async.wait_group %0;" :: "n"(1) : "memory");
        __syncthreads();

        if (c + 2 < NCH) {
            uint32_t sbp = smem_u32(dyn + ((c + 2) % 3) * STG1);
            size_t ko = (size_t)(c + 2) * 32;
            cp16(sbp + s0,             pA  + g0 + ko);
            cp16(sbp + s1,             pA  + g1 + ko);
            cp16(sbp + RGN32 + s0,     pBg + g0 + ko);
            cp16(sbp + RGN32 + s1,     pBg + g1 + ko);
            cp16(sbp + 2 * RGN32 + s0, pBu + g0 + ko);
            cp16(sbp + 2 * RGN32 + s1, pBu + g1 + ko);
        }
        asm volatile("cp.async.commit_group;" ::: "memory");

        uint32_t sb = smem_u32(dyn + (c % 3) * STG1);

        #pragma unroll
        for (int ks = 0; ks < 2; ks++) {
            int acc_c = ks * 2 + a_hc;
            int b_c   = ks * 2 + b_hc;
            uint32_t bg[8], bu[8];
            #pragma unroll
            for (int j = 0; j < 2; j++) {
                int brow = wn * 32 + (2 * j + b_fr) * 8 + b_rl;
                uint32_t ba = sb + RGN32 + swz32(brow, b_c);
                ldsm4(bg[4 * j], bg[4 * j + 1], bg[4 * j + 2], bg[4 * j + 3], ba);
                ldsm4(bu[4 * j], bu[4 * j + 1], bu[4 * j + 2], bu[4 * j + 3], ba + RGN32);
            }
            #pragma unroll
            for (int mf = 0; mf < 4; mf++) {
                int arow = wm * 64 + mf * 16 + a_rl;
                uint32_t ah[4];
                ldsm4(ah[0], ah[1], ah[2], ah[3], sb + swz32(arow, acc_c));
                #pragma unroll
                for (int nf = 0; nf < 4; nf++) {
                    mma16816(accg[mf][nf], ah, bg[2 * nf], bg[2 * nf + 1]);
                    mma16816(accu[mf][nf], ah, bu[2 * nf], bu[2 * nf + 1]);
                }
            }
        }
    }

    __half* Ca = g_acth + ((size_t)e * CAP + m0) * H_ + n0;
    #pragma unroll
    for (int mf = 0; mf < 4; mf++)
        #pragma unroll
        for (int nf = 0; nf < 4; nf++) {
            int r0 = wm * 64 + mf * 16 + g;
            int col = wn * 32 + nf * 8 + q * 2;
            float a0 = silu_mul(accg[mf][nf][0], accu[mf][nf][0]);
            float a1 = silu_mul(accg[mf][nf][1], accu[mf][nf][1]);
            float a2 = silu_mul(accg[mf][nf][2], accu[mf][nf][2]);
            float a3 = silu_mul(accg[mf][nf][3], accu[mf][nf][3]);
            *(__half2*)(Ca + (size_t)r0 * H_ + col)       = __floats2half2_rn(a0, a1);
            *(__half2*)(Ca + (size_t)(r0 + 8) * H_ + col) = __floats2half2_rn(a2, a3);
        }
}

// ---------------- 5) GEMM2 (ldmatrix, BN=256, KCH=32, 3-stage) -------------
__global__ __launch_bounds__(256) void gemm2_mma()
{
    extern __shared__ __align__(16) char dyn[];

    const int K = H_, Ntot = D_;
    int e = blockIdx.z;
    int m0 = blockIdx.y * 128;
    if (m0 >= g_cnt[e]) return;
    int n0 = blockIdx.x * 256;

    int tid = threadIdx.x, lane = tid & 31, wid = tid >> 5;
    int wm = wid & 1, wn = wid >> 1;
    int g = lane >> 2, q = lane & 3;

    const __half* pA = g_acth + ((size_t)e * CAP + m0) * K;
    const __half* pB = g_w2h  + ((size_t)e * Ntot + n0) * K;

    float acc[4][8][4];
    #pragma unroll
    for (int i = 0; i < 4; i++)
        #pragma unroll
        for (int j = 0; j < 8; j++)
            #pragma unroll
            for (int p = 0; p < 4; p++) acc[i][j][p] = 0.f;

    // A loader: 2 chunk-slots/thread (128 rows x 4 chunks)
    int i0_ld = tid * 2, i1_ld = tid * 2 + 1;
    int ar0 = i0_ld >> 2, ac0 = i0_ld & 3;
    int ar1 = i1_ld >> 2, ac1 = i1_ld & 3;
    uint32_t as0 = swz32(ar0, ac0), as1 = swz32(ar1, ac1);
    size_t ag0 = (size_t)ar0 * K + ac0 * 8;
    size_t ag1 = (size_t)ar1 * K + ac1 * 8;
    // B loader: row = tid (256 rows), 4 chunks each
    uint32_t bs[4];
    #pragma unroll
    for (int j = 0; j < 4; j++) bs[j] = RGN32 + swz32(tid, j);
    size_t bg_ld = (size_t)tid * K;

    int a_rl = (lane & 7) + ((lane >> 3) & 1) * 8;
    int a_hc = lane >> 4;
    int b_rl = lane & 7;
    int b_fr = lane >> 4;
    int b_hc = (lane >> 3) & 1;

    const int NCH = K >> 5;   // 64

    #pragma unroll
    for (int c = 0; c < 2; c++) {
        uint32_t sb = smem_u32(dyn + c * STG2);
        size_t ko = (size_t)c * 32;
        cp16(sb + as0, pA + ag0 + ko);
        cp16(sb + as1, pA + ag1 + ko);
        #pragma unroll
        for (int j = 0; j < 4; j++) cp16(sb + bs[j], pB + bg_ld + ko + j * 8);
        asm volatile("cp.async.commit_group;" ::: "memory");
    }

    for (int c = 0; c < NCH; c++) {
        asm volatile("cp.async.wait_group %0;" :: "n"(1) : "memory");
        __syncthreads();

        if (c + 2 < NCH) {
            uint32_t sbp = smem_u32(dyn + ((c + 2) % 3) * STG2);
            size_t ko = (size_t)(c + 2) * 32;
            cp16(sbp + as0, pA + ag0 + ko);
            cp16(sbp + as1, pA + ag1 + ko);
            #pragma unroll
            for (int j = 0; j < 4; j++) cp16(sbp + bs[j], pB + bg_ld + ko + j * 8);
        }
        asm volatile("cp.async.commit_group;" ::: "memory");

        uint32_t sb = smem_u32(dyn + (c % 3) * STG2);

        #pragma unroll
        for (int ks = 0; ks < 2; ks++) {
            int acc_c = ks * 2 + a_hc;
            int b_c   = ks * 2 + b_hc;
            uint32_t bf[16];
            #pragma unroll
            for (int j = 0; j < 4; j++) {
                int brow = wn * 64 + (2 * j + b_fr) * 8 + b_rl;
                ldsm4(bf[4 * j], bf[4 * j + 1], bf[4 * j + 2], bf[4 * j + 3],
                      sb + RGN32 + swz32(brow, b_c));
            }
            #pragma unroll
            for (int mf = 0; mf < 4; mf++) {
                int arow = wm * 64 + mf * 16 + a_rl;
                uint32_t ah[4];
                ldsm4(ah[0], ah[1], ah[2], ah[3], sb + swz32(arow, acc_c));
                #pragma unroll
                for (int nf = 0; nf < 8; nf++)
                    mma16816(acc[mf][nf], ah, bf[2 * nf], bf[2 * nf + 1]);
            }
        }
    }

    float* C = g_ffn + ((size_t)e * CAP + m0) * Ntot + n0;
    #pragma unroll
    for (int mf = 0; mf < 4; mf++)
        #pragma unroll
        for (int nf = 0; nf < 8; nf++) {
            int r0 = wm * 64 + mf * 16 + g;
            int col = wn * 64 + nf * 8 + q * 2;
            *(float2*)(C + (size_t)r0 * Ntot + col) =
                make_float2(acc[mf][nf][0], acc[mf][nf][1]);
            *(float2*)(C + (size_t)(r0 + 8) * Ntot + col) =
                make_float2(acc[mf][nf][2], acc[mf][nf][3]);
        }
}

// ---------------- 6) combine ----------------
__global__ void combine_kernel(const float* __restrict__ x, float* __restrict__ out) {
    int t = blockIdx.x;
    int s0 = g_slot[2 * t], s1 = g_slot[2 * t + 1];
    float w0 = g_weight[2 * t], w1 = g_weight[2 * t + 1];
    int i = threadIdx.x;  // 192
    float4 xv = ((const float4*)(x + (size_t)t * D_))[i];
    float rx = 0.f, ry = 0.f, rz = 0.f, rw = 0.f;
    if (s0 >= 0) {
        float4 f = ((const float4*)(g_ffn + (size_t)s0 * D_))[i];
        rx += w0 * (xv.x + f.x); ry += w0 * (xv.y + f.y);
        rz += w0 * (xv.z + f.z); rw += w0 * (xv.w + f.w);
    }
    if (s1 >= 0) {
        float4 f = ((const float4*)(g_ffn + (size_t)s1 * D_))[i];
        rx += w1 * (xv.x + f.x); ry += w1 * (xv.y + f.y);
        rz += w1 * (xv.z + f.z); rw += w1 * (xv.w + f.w);
    }
    ((float4*)(out + (size_t)t * D_))[i] = make_float4(rx, ry, rz, rw);
}

// ---------------- launch (NO __device__ symbols cross the host ABI) --------
extern "C" void kernel_launch(void* const* d_in, const int* in_sizes, int n_in,
                              void* d_out, int out_size) {
    const float* x      = (const float*)d_in[0];
    const float* gate_w = (const float*)d_in[1];
    const float* w13    = (const float*)d_in[2];
    const float* w2     = (const float*)d_in[3];
    const float* norm_w = (const float*)d_in[4];
    float* out = (float*)d_out;

    cudaFuncSetAttribute(gemm1_silu, cudaFuncAttributeMaxDynamicSharedMemorySize, DSMEM);
    cudaFuncSetAttribute(gemm2_mma,  cudaFuncAttributeMaxDynamicSharedMemorySize, DSMEM);

    router_kernel<<<NT / 8, 256>>>(x, gate_w);
    scan_kernel<<<E_, 256>>>();
    dispatch_kernel<<<E_ * CAP, 192>>>(x, norm_w);

    cvt_kernel<<<(E_ * N13 * D_) / 1024, 256>>>(w13, 0);
    cvt_kernel<<<(E_ * D_ * H_) / 1024, 256>>>(w2, 1);

    dim3 g1(H_ / 128, CAP / 128, E_);    // (16, 40, 8): dual-tile gate+up
    gemm1_silu<<<g1, 256, DSMEM>>>();

    dim3 g2(D_ / 256, CAP / 128, E_);    // (3, 40, 8)
    gemm2_mma<<<g2, 256, DSMEM>>>();

    combine_kernel<<<NT, 192>>>(x, out);
}